// round 15
// baseline (speedup 1.0000x reference)
#include <cuda_runtime.h>
#include <cuda_fp16.h>
#include <cstdint>

// ===========================================================================
// SparseResBlock3D — dense mma.sync fp16 (fp32 accumulate).
// Single 512-thread CTA: 256 rows x 128 cols, 16 warps (m32n64 warp tiles).
// Chunk = whole tap (K=128) as two K=64 sub-tiles; NSTAGE=2 (27 barriers).
// B staged once per 256 rows (-25% smem stores, -50% B L2 reads vs 2-CTA).
//   film = silu(emb) @ emb_W + emb_b
//   h1   = fp16(silu(LN(feats; g,b)))                      -> g_bufA
//   h3   = fp16(silu(LN(conv27(h1,W1)+b1)*(1+s[b])+sh[b])) -> g_bufH3 (fused)
//   out  = conv27(h3, W2) + b2 + feats
// ===========================================================================

#define NROWS     200000
#define C         128
#define TAPS      27
#define ROWS_CTA  256          // CTA output tile rows
#define NTHREADS  512
#define NSTAGE    2
#define STAGE_BYTES 98304      // A0(32K)+A1(32K)+B0(16K)+B1(16K)
#define OFF_B       65536      // B region offset within a stage
#define STAGES_OFF  28672      // idx region: 256*27*4 = 27648B, padded
#define DYN_SMEM  (STAGES_OFF + NSTAGE * STAGE_BYTES)   // 225280 B
#define ACC_PITCH 132          // fp32 epilogue tile pitch (floats)

// ---- scratch (static device globals) ----
__device__ __half g_bufA[(size_t)NROWS * C];    // fp16 h1 (conv1 input)
__device__ __half g_bufH3[(size_t)NROWS * C];   // fp16 h3 (conv2 input)
__device__ float  g_film[4 * 256];              // [b][0:128]=1+scale, [128:256]=shift
__device__ __half g_WT1[(size_t)54 * 8192];     // pre-swizzled fp16 W^T (16KB per (tap,khalf))
__device__ __half g_WT2[(size_t)54 * 8192];

// ---------------------------------------------------------------------------
// helpers
// ---------------------------------------------------------------------------
__device__ __forceinline__ float silu_f(float x) { return x / (1.0f + expf(-x)); }

__device__ __forceinline__ uint32_t smem_u32(const void* p) {
    uint32_t a;
    asm("{ .reg .u64 t; cvta.to.shared.u64 t, %1; cvt.u32.u64 %0, t; }" : "=r"(a) : "l"(p));
    return a;
}

__device__ __forceinline__ void cp_async16(uint32_t dst, const void* src, int src_bytes) {
    asm volatile("cp.async.cg.shared.global [%0], [%1], 16, %2;"
                 :: "r"(dst), "l"(src), "r"(src_bytes));
}
__device__ __forceinline__ void cp_commit() {
    asm volatile("cp.async.commit_group;");
}
template <int N> __device__ __forceinline__ void cp_wait() {
    asm volatile("cp.async.wait_group %0;" :: "n"(N));
}

__device__ __forceinline__ void ldsm4(uint32_t* r, uint32_t addr) {
    asm volatile("ldmatrix.sync.aligned.m8n8.x4.shared.b16 {%0,%1,%2,%3}, [%4];"
                 : "=r"(r[0]), "=r"(r[1]), "=r"(r[2]), "=r"(r[3]) : "r"(addr));
}

__device__ __forceinline__ void mma_f16(float* d, const uint32_t* a,
                                        uint32_t b0, uint32_t b1) {
    asm volatile(
        "mma.sync.aligned.m16n8k16.row.col.f32.f16.f16.f32 "
        "{%0,%1,%2,%3}, {%4,%5,%6,%7}, {%8,%9}, {%0,%1,%2,%3};"
        : "+f"(d[0]), "+f"(d[1]), "+f"(d[2]), "+f"(d[3])
        : "r"(a[0]), "r"(a[1]), "r"(a[2]), "r"(a[3]), "r"(b0), "r"(b1));
}

// ---------------------------------------------------------------------------
// FiLM embedding GEMM.  grid=(4), block=256.
// ---------------------------------------------------------------------------
__global__ void film_kernel(const float* __restrict__ emb,
                            const float* __restrict__ embW,
                            const float* __restrict__ embb) {
    __shared__ float s[512];
    int b = blockIdx.x;
    int c = threadIdx.x;
    for (int e = c; e < 512; e += 256) s[e] = silu_f(emb[b * 512 + e]);
    __syncthreads();
    float acc = embb[c];
#pragma unroll 8
    for (int e = 0; e < 512; ++e) acc = fmaf(s[e], embW[e * 256 + c], acc);
    g_film[b * 256 + c] = (c < 128) ? (1.0f + acc) : acc;
}

// ---------------------------------------------------------------------------
// LN(gamma,beta) + SiLU -> fp16 g_bufA.  One warp per row.
// ---------------------------------------------------------------------------
__global__ void ln_silu_kernel(const float* __restrict__ x,
                               const float* __restrict__ gamma,
                               const float* __restrict__ beta) {
    int row  = blockIdx.x * 8 + (threadIdx.x >> 5);
    int lane = threadIdx.x & 31;
    float4 v = reinterpret_cast<const float4*>(x + (size_t)row * C)[lane];
    float s  = v.x + v.y + v.z + v.w;
    float ss = v.x * v.x + v.y * v.y + v.z * v.z + v.w * v.w;
#pragma unroll
    for (int o = 16; o > 0; o >>= 1) {
        s  += __shfl_xor_sync(0xffffffffu, s, o);
        ss += __shfl_xor_sync(0xffffffffu, ss, o);
    }
    float mu  = s * (1.0f / 128.0f);
    float inv = rsqrtf(ss * (1.0f / 128.0f) - mu * mu + 1e-6f);
    float4 g  = reinterpret_cast<const float4*>(gamma)[lane];
    float4 be = reinterpret_cast<const float4*>(beta)[lane];
    __half2 h0 = __floats2half2_rn(silu_f((v.x - mu) * inv * g.x + be.x),
                                   silu_f((v.y - mu) * inv * g.y + be.y));
    __half2 h1 = __floats2half2_rn(silu_f((v.z - mu) * inv * g.z + be.z),
                                   silu_f((v.w - mu) * inv * g.w + be.w));
    __half2* dst = reinterpret_cast<__half2*>(g_bufA + (size_t)row * C);
    dst[lane * 2]     = h0;
    dst[lane * 2 + 1] = h1;
}

// ---------------------------------------------------------------------------
// Weight prep: transpose to [N,K], fp16-round, XOR-swizzle, pack per
// (tap, k-half) chunk of 16KB (128 n-rows x 64 k fp16 = 128B rows).
// ---------------------------------------------------------------------------
__global__ void wprep_kernel(const float* __restrict__ W, __half* __restrict__ WT) {
    int c = blockIdx.x;
    int k = c >> 1, q = c & 1;
    for (int e = threadIdx.x; e < 8192; e += 256) {
        int nn = e >> 6, w = e & 63;
        __half v = __float2half_rn(W[((size_t)k * 128 + q * 64 + w) * 128 + nn]);
        int off = nn * 128 + w * 2;                       // byte offset in tile
        WT[(size_t)c * 8192 + ((off ^ ((off >> 3) & 0x70)) >> 1)] = v;
    }
}

// ---------------------------------------------------------------------------
// Dense mma.sync fp16 sparse conv. 512 threads (16 warps), CTA 256x128.
// Warp tile m32 x n64 (8 m-warps x 2 n-warps). 2-stage pipeline over 27
// whole-tap chunks (K=128 as two K=64 sub-tiles); one barrier per tap.
// ---------------------------------------------------------------------------
template <bool FUSE_LN>
__global__ void __launch_bounds__(NTHREADS, 1)
conv_mma_kernel(const __half* __restrict__ src,
                const int*    __restrict__ nbr,
                const __half* __restrict__ WT,
                const float*  __restrict__ bias,
                const float*  __restrict__ residual,
                float*        __restrict__ out,
                __half*       __restrict__ h3_out,
                const int*    __restrict__ batch_idx,
                int n) {
    extern __shared__ char dsm[];
    int* idxsh = reinterpret_cast<int*>(dsm);

    const int tid  = threadIdx.x;
    const int wid  = tid >> 5;
    const int lane = tid & 31;
    const int row0 = blockIdx.x * ROWS_CTA;
    const uint32_t dsm_u32 = smem_u32(dsm);

    // --- stage neighbor indices (tail rows forced invalid) ---
    for (int l = tid; l < ROWS_CTA * TAPS; l += NTHREADS) {
        int gr = row0 + l / TAPS;
        idxsh[l] = (gr < n) ? nbr[(size_t)gr * TAPS + (l % TAPS)] : -1;
    }
    __syncthreads();

    // loader: A: 2 threads/row, thread (r, h) fills sub-tile h's row r (128B).
    //         B: 32KB, thread t fills sub-tile t>>8, 64B.
    const int a_row  = tid >> 1;
    const int a_sub  = tid & 1;
    const int b_sub  = tid >> 8;
    const int b_tid  = tid & 255;

    auto load_chunk = [&](int k) {
        uint32_t sb = dsm_u32 + STAGES_OFF + (k & 1) * STAGE_BYTES;
        int idx = idxsh[a_row * TAPS + k];
        const __half* srow = src + (size_t)(idx < 0 ? 0 : idx) * C + a_sub * 64;
        int bytes = (idx < 0) ? 0 : 16;
        uint32_t adst = sb + a_sub * 32768;
#pragma unroll
        for (int i = 0; i < 8; ++i) {
            int off = a_row * 128 + i * 16;
            cp_async16(adst + (off ^ ((off >> 3) & 0x70)), srow + i * 8, bytes);
        }
        const __half* bsrc = WT + (size_t)(2 * k + b_sub) * 8192 + b_tid * 32;
        uint32_t bd = sb + OFF_B + b_sub * 16384 + b_tid * 64;
#pragma unroll
        for (int i = 0; i < 4; ++i) cp_async16(bd + i * 16, bsrc + i * 8, 16);
        cp_commit();
    };

    // --- warp tiling: wm=wid&7 -> rows 32*wm ; wn=wid>>3 -> cols 64*wn ---
    const int wm = wid & 7;
    const int wn = wid >> 3;

    uint32_t a_rowoff[2];
    int      a_ph[2];
#pragma unroll
    for (int mt = 0; mt < 2; ++mt) {
        int r = 32 * wm + 16 * mt + (lane & 15);
        a_rowoff[mt] = r * 128;
        a_ph[mt]     = r & 7;
    }
    const int a_kbh = lane >> 4;

    uint32_t b_rowoff[4];
    int      b_ph[4];
#pragma unroll
    for (int np = 0; np < 4; ++np) {
        int r = 64 * wn + 16 * np + (lane & 7) + ((lane >> 4) << 3);
        b_rowoff[np] = OFF_B + r * 128;
        b_ph[np]     = r & 7;
    }
    const int b_kbh = (lane >> 3) & 1;

    float d[2][8][4];
#pragma unroll
    for (int mt = 0; mt < 2; ++mt)
#pragma unroll
        for (int nt = 0; nt < 8; ++nt)
#pragma unroll
            for (int j = 0; j < 4; ++j) d[mt][nt][j] = 0.0f;

    // prologue
    load_chunk(0);

    for (int k = 0; k < TAPS; ++k) {
        cp_wait<0>();
        __syncthreads();

        if (k + 1 < TAPS) load_chunk(k + 1);   // prefetch BEFORE compute

        uint32_t sb = dsm_u32 + STAGES_OFF + (k & 1) * STAGE_BYTES;

#pragma unroll
        for (int ks = 0; ks < 8; ++ks) {              // 8 x k16 = K128
            const uint32_t asub = sb + (ks >> 2) * 32768;
            const uint32_t bsub = sb + (ks >> 2) * 16384;
            const int ksl = ks & 3;
            uint32_t a0[4], a1[4];
            ldsm4(a0, asub + a_rowoff[0] + ((((ksl << 1) | a_kbh) ^ a_ph[0]) << 4));
            ldsm4(a1, asub + a_rowoff[1] + ((((ksl << 1) | a_kbh) ^ a_ph[1]) << 4));
#pragma unroll
            for (int np = 0; np < 4; ++np) {
                uint32_t b[4];
                ldsm4(b, bsub + b_rowoff[np] + ((((ksl << 1) | b_kbh) ^ b_ph[np]) << 4));
                mma_f16(d[0][2 * np],     a0, b[0], b[1]);
                mma_f16(d[0][2 * np + 1], a0, b[2], b[3]);
                mma_f16(d[1][2 * np],     a1, b[0], b[1]);
                mma_f16(d[1][2 * np + 1], a1, b[2], b[3]);
            }
        }
        // no trailing barrier: next iteration's barrier provides the fence
    }

    const int qr = lane >> 2;            // 0..7
    const int qc = (lane & 3) * 2;       // 0,2,4,6

    if (!FUSE_LN) {
        // --- epilogue: out = acc + bias + residual (fp32) ---
#pragma unroll
        for (int mt = 0; mt < 2; ++mt) {
#pragma unroll
            for (int nt = 0; nt < 8; ++nt) {
                int gc = 64 * wn + 8 * nt + qc;
                float2 bb = *reinterpret_cast<const float2*>(bias + gc);
                int gr0 = row0 + 32 * wm + 16 * mt + qr;
                int gr1 = gr0 + 8;
                if (gr0 < n) {
                    float2 o = make_float2(d[mt][nt][0] + bb.x, d[mt][nt][1] + bb.y);
                    size_t off = (size_t)gr0 * C + gc;
                    float2 r = *reinterpret_cast<const float2*>(residual + off);
                    o.x += r.x; o.y += r.y;
                    *reinterpret_cast<float2*>(out + off) = o;
                }
                if (gr1 < n) {
                    float2 o = make_float2(d[mt][nt][2] + bb.x, d[mt][nt][3] + bb.y);
                    size_t off = (size_t)gr1 * C + gc;
                    float2 r = *reinterpret_cast<const float2*>(residual + off);
                    o.x += r.x; o.y += r.y;
                    *reinterpret_cast<float2*>(out + off) = o;
                }
            }
        }
    } else {
        // --- fused epilogue: stage acc+bias to smem, LN+FiLM+SiLU -> fp16 ---
        float* accs = reinterpret_cast<float*>(dsm);   // 256 x ACC_PITCH fp32
        __syncthreads();   // all warps done with smem stages & idxsh
#pragma unroll
        for (int mt = 0; mt < 2; ++mt) {
#pragma unroll
            for (int nt = 0; nt < 8; ++nt) {
                int col = 64 * wn + 8 * nt + qc;
                float2 bb = *reinterpret_cast<const float2*>(bias + col);
                int r0 = 32 * wm + 16 * mt + qr;
                float* p0 = accs + r0 * ACC_PITCH + col;
                p0[0] = d[mt][nt][0] + bb.x;
                p0[1] = d[mt][nt][1] + bb.y;
                float* p1 = accs + (r0 + 8) * ACC_PITCH + col;
                p1[0] = d[mt][nt][2] + bb.x;
                p1[1] = d[mt][nt][3] + bb.y;
            }
        }
        __syncthreads();
        // each warp LNs 16 rows; lane holds 4 consecutive floats of the row
#pragma unroll
        for (int rr = 0; rr < 16; ++rr) {
            int r  = wid * 16 + rr;
            int gr = row0 + r;
            if (gr < n) {
                const float* row = accs + r * ACC_PITCH;
                float4 v = *reinterpret_cast<const float4*>(row + lane * 4);
                float s  = v.x + v.y + v.z + v.w;
                float ss = v.x * v.x + v.y * v.y + v.z * v.z + v.w * v.w;
#pragma unroll
                for (int o = 16; o > 0; o >>= 1) {
                    s  += __shfl_xor_sync(0xffffffffu, s, o);
                    ss += __shfl_xor_sync(0xffffffffu, ss, o);
                }
                float mu  = s * (1.0f / 128.0f);
                float inv = rsqrtf(ss * (1.0f / 128.0f) - mu * mu + 1e-6f);
                int b = batch_idx[gr];
                float4 sc = *reinterpret_cast<const float4*>(&g_film[b * 256 + lane * 4]);
                float4 sh = *reinterpret_cast<const float4*>(&g_film[b * 256 + 128 + lane * 4]);
                __half2 h0 = __floats2half2_rn(silu_f((v.x - mu) * inv * sc.x + sh.x),
                                               silu_f((v.y - mu) * inv * sc.y + sh.y));
                __half2 h1 = __floats2half2_rn(silu_f((v.z - mu) * inv * sc.z + sh.z),
                                               silu_f((v.w - mu) * inv * sc.w + sh.w));
                __half2* dst = reinterpret_cast<__half2*>(h3_out + (size_t)gr * C);
                dst[lane * 2]     = h0;
                dst[lane * 2 + 1] = h1;
            }
        }
    }
}

// ---------------------------------------------------------------------------
// Host launcher. conv1 is the 4th launch (the one the profiler captures).
// ---------------------------------------------------------------------------
extern "C" void kernel_launch(void* const* d_in, const int* in_sizes, int n_in,
                              void* d_out, int out_size) {
    const float* feats = (const float*)d_in[0];
    const float* emb   = (const float*)d_in[1];
    const float* g1    = (const float*)d_in[2];
    const float* b1    = (const float*)d_in[3];
    const float* W1    = (const float*)d_in[4];
    const float* cb1   = (const float*)d_in[5];
    const float* W2    = (const float*)d_in[6];
    const float* cb2   = (const float*)d_in[7];
    const float* embW  = (const float*)d_in[8];
    const float* embb  = (const float*)d_in[9];
    const int*   nbr   = (const int*)d_in[10];
    const int*   bidx  = (const int*)d_in[11];
    float*       out   = (float*)d_out;
    (void)n_in; (void)out_size;

    const int n    = in_sizes[0] / C;                  // 200000
    const int nblk = (n + ROWS_CTA - 1) / ROWS_CTA;    // 782

    cudaFuncSetAttribute(conv_mma_kernel<true>,
                         cudaFuncAttributeMaxDynamicSharedMemorySize, DYN_SMEM);
    cudaFuncSetAttribute(conv_mma_kernel<false>,
                         cudaFuncAttributeMaxDynamicSharedMemorySize, DYN_SMEM);

    __half *bufA, *bufH3, *wt1, *wt2;
    cudaGetSymbolAddress((void**)&bufA, g_bufA);
    cudaGetSymbolAddress((void**)&bufH3, g_bufH3);
    cudaGetSymbolAddress((void**)&wt1, g_WT1);
    cudaGetSymbolAddress((void**)&wt2, g_WT2);

    wprep_kernel<<<54, 256>>>(W1, wt1);                                    // 1
    ln_silu_kernel<<<n / 8, 256>>>(feats, g1, b1);                         // 2
    film_kernel<<<4, 256>>>(emb, embW, embb);                              // 3
    conv_mma_kernel<true><<<nblk, NTHREADS, DYN_SMEM>>>(bufA, nbr, wt1,    // 4 (profiled)
                                                        cb1, nullptr, nullptr,
                                                        bufH3, bidx, n);
    wprep_kernel<<<54, 256>>>(W2, wt2);                                    // 5
    conv_mma_kernel<false><<<nblk, NTHREADS, DYN_SMEM>>>(bufH3, nbr, wt2,  // 6
                                                         cb2, feats, out,
                                                         nullptr, nullptr, n);
}

// round 17
// speedup vs baseline: 1.0367x; 1.0367x over previous
#include <cuda_runtime.h>
#include <cuda_fp16.h>
#include <cstdint>

// ===========================================================================
// SparseResBlock3D — dense mma.sync fp16 (fp32 accumulate), R10 structure:
// CTA 128x128, 8 warps m32n64, 3-stage cp.async pipeline, 2 CTAs/SM.
// conv1 fuses LN+FiLM+SiLU via shuffle-based row stats (no smem round-trip).
//   film/wprep fused into one prep kernel.
//   h1   = fp16(silu(LN(feats; g,b)))                      -> g_bufA
//   h3   = fp16(silu(LN(conv27(h1,W1)+b1)*(1+s[b])+sh[b])) -> g_bufH3 (fused)
//   out  = conv27(h3, W2) + b2 + feats
// ===========================================================================

#define NROWS     200000
#define C         128
#define TAPS      27
#define ROWS_CTA  128
#define NC        54           // 27 taps * 2 (K=64 each)
#define NSTAGE    3
#define STAGE_BYTES 32768      // A(16K) + B(16K)
#define STAGES_OFF  14336      // idx region: 128*27*4 = 13824B, padded
#define DYN_SMEM  (STAGES_OFF + NSTAGE * STAGE_BYTES)   // 112640 B

// ---- scratch (static device globals) ----
__device__ __half g_bufA[(size_t)NROWS * C];    // fp16 h1 (conv1 input)
__device__ __half g_bufH3[(size_t)NROWS * C];   // fp16 h3 (conv2 input)
__device__ float  g_film[4 * 256];              // [b][0:128]=1+scale, [128:256]=shift
__device__ __half g_WT1[(size_t)NC * 8192];     // pre-swizzled fp16 W^T chunks
__device__ __half g_WT2[(size_t)NC * 8192];

// ---------------------------------------------------------------------------
// helpers
// ---------------------------------------------------------------------------
__device__ __forceinline__ float silu_f(float x) { return x / (1.0f + expf(-x)); }

__device__ __forceinline__ uint32_t smem_u32(const void* p) {
    uint32_t a;
    asm("{ .reg .u64 t; cvta.to.shared.u64 t, %1; cvt.u32.u64 %0, t; }" : "=r"(a) : "l"(p));
    return a;
}

__device__ __forceinline__ void cp_async16(uint32_t dst, const void* src, int src_bytes) {
    asm volatile("cp.async.cg.shared.global [%0], [%1], 16, %2;"
                 :: "r"(dst), "l"(src), "r"(src_bytes));
}
__device__ __forceinline__ void cp_async16_ca(uint32_t dst, const void* src) {
    asm volatile("cp.async.ca.shared.global [%0], [%1], 16;"
                 :: "r"(dst), "l"(src));
}
__device__ __forceinline__ void cp_commit() {
    asm volatile("cp.async.commit_group;");
}
template <int N> __device__ __forceinline__ void cp_wait() {
    asm volatile("cp.async.wait_group %0;" :: "n"(N));
}

__device__ __forceinline__ void ldsm4(uint32_t* r, uint32_t addr) {
    asm volatile("ldmatrix.sync.aligned.m8n8.x4.shared.b16 {%0,%1,%2,%3}, [%4];"
                 : "=r"(r[0]), "=r"(r[1]), "=r"(r[2]), "=r"(r[3]) : "r"(addr));
}

__device__ __forceinline__ void mma_f16(float* d, const uint32_t* a,
                                        uint32_t b0, uint32_t b1) {
    asm volatile(
        "mma.sync.aligned.m16n8k16.row.col.f32.f16.f16.f32 "
        "{%0,%1,%2,%3}, {%4,%5,%6,%7}, {%8,%9}, {%0,%1,%2,%3};"
        : "+f"(d[0]), "+f"(d[1]), "+f"(d[2]), "+f"(d[3])
        : "r"(a[0]), "r"(a[1]), "r"(a[2]), "r"(a[3]), "r"(b0), "r"(b1));
}

// ---------------------------------------------------------------------------
// Prep kernel: blocks 0-53 -> wprep W1; 54-107 -> wprep W2; 108-111 -> film.
// ---------------------------------------------------------------------------
__device__ __forceinline__ void wprep_body(const float* __restrict__ W,
                                           __half* __restrict__ WT, int c) {
    int k = c >> 1, q = c & 1;
    for (int e = threadIdx.x; e < 8192; e += 256) {
        int nn = e >> 6, w = e & 63;
        __half v = __float2half_rn(W[((size_t)k * 128 + q * 64 + w) * 128 + nn]);
        int off = nn * 128 + w * 2;
        WT[(size_t)c * 8192 + ((off ^ ((off >> 3) & 0x70)) >> 1)] = v;
    }
}

__global__ void prep_kernel(const float* __restrict__ W1,
                            const float* __restrict__ W2,
                            const float* __restrict__ emb,
                            const float* __restrict__ embW,
                            const float* __restrict__ embb) {
    int bid = blockIdx.x;
    if (bid < NC) {
        wprep_body(W1, g_WT1, bid);
    } else if (bid < 2 * NC) {
        wprep_body(W2, g_WT2, bid - NC);
    } else {
        __shared__ float s[512];
        int b = bid - 2 * NC;
        int c = threadIdx.x;
        for (int e = c; e < 512; e += 256) s[e] = silu_f(emb[b * 512 + e]);
        __syncthreads();
        float acc = embb[c];
#pragma unroll 8
        for (int e = 0; e < 512; ++e) acc = fmaf(s[e], embW[e * 256 + c], acc);
        g_film[b * 256 + c] = (c < 128) ? (1.0f + acc) : acc;
    }
}

// ---------------------------------------------------------------------------
// LN(gamma,beta) + SiLU -> fp16 g_bufA.  One warp per row.
// ---------------------------------------------------------------------------
__global__ void ln_silu_kernel(const float* __restrict__ x,
                               const float* __restrict__ gamma,
                               const float* __restrict__ beta) {
    int row  = blockIdx.x * 8 + (threadIdx.x >> 5);
    int lane = threadIdx.x & 31;
    float4 v = reinterpret_cast<const float4*>(x + (size_t)row * C)[lane];
    float s  = v.x + v.y + v.z + v.w;
    float ss = v.x * v.x + v.y * v.y + v.z * v.z + v.w * v.w;
#pragma unroll
    for (int o = 16; o > 0; o >>= 1) {
        s  += __shfl_xor_sync(0xffffffffu, s, o);
        ss += __shfl_xor_sync(0xffffffffu, ss, o);
    }
    float mu  = s * (1.0f / 128.0f);
    float inv = rsqrtf(ss * (1.0f / 128.0f) - mu * mu + 1e-6f);
    float4 g  = reinterpret_cast<const float4*>(gamma)[lane];
    float4 be = reinterpret_cast<const float4*>(beta)[lane];
    __half2 h0 = __floats2half2_rn(silu_f((v.x - mu) * inv * g.x + be.x),
                                   silu_f((v.y - mu) * inv * g.y + be.y));
    __half2 h1 = __floats2half2_rn(silu_f((v.z - mu) * inv * g.z + be.z),
                                   silu_f((v.w - mu) * inv * g.w + be.w));
    __half2* dst = reinterpret_cast<__half2*>(g_bufA + (size_t)row * C);
    dst[lane * 2]     = h0;
    dst[lane * 2 + 1] = h1;
}

// ---------------------------------------------------------------------------
// Dense mma.sync fp16 sparse conv. 256 threads (8 warps), CTA 128x128.
// Warp tile m32 x n64. 3-stage cp.async pipeline, one barrier per chunk.
// FUSE_LN=1: shuffle-based LN+FiLM+SiLU epilogue -> fp16 h3_out.
// FUSE_LN=0: acc + bias + residual -> fp32 out.
// ---------------------------------------------------------------------------
template <bool FUSE_LN>
__global__ void __launch_bounds__(256, 2)
conv_mma_kernel(const __half* __restrict__ src,
                const int*    __restrict__ nbr,
                const __half* __restrict__ WT,
                const float*  __restrict__ bias,
                const float*  __restrict__ residual,
                float*        __restrict__ out,
                __half*       __restrict__ h3_out,
                const int*    __restrict__ batch_idx,
                int n) {
    extern __shared__ char dsm[];
    int* idxsh = reinterpret_cast<int*>(dsm);

    const int tid  = threadIdx.x;
    const int wid  = tid >> 5;
    const int lane = tid & 31;
    const int row0 = blockIdx.x * ROWS_CTA;
    const uint32_t dsm_u32 = smem_u32(dsm);

    // --- stage neighbor indices (tail rows forced invalid) ---
    for (int l = tid; l < ROWS_CTA * TAPS; l += 256) {
        int gr = row0 + l / TAPS;
        idxsh[l] = (gr < n) ? nbr[(size_t)gr * TAPS + (l % TAPS)] : -1;
    }
    __syncthreads();

    // loader constants: 2 threads per row, 64B each
    const int a_row  = tid >> 1;
    const int a_half = tid & 1;

    auto load_chunk = [&](int c) {
        int st = c % NSTAGE;
        uint32_t sb = dsm_u32 + STAGES_OFF + st * STAGE_BYTES;
        int k = c >> 1, q = c & 1;
        int idx = idxsh[a_row * TAPS + k];
        const __half* srow = src + (size_t)(idx < 0 ? 0 : idx) * C + q * 64 + a_half * 32;
        int bytes = (idx < 0) ? 0 : 16;
#pragma unroll
        for (int i = 0; i < 4; ++i) {
            int off = a_row * 128 + a_half * 64 + i * 16;
            cp_async16(sb + (off ^ ((off >> 3) & 0x70)), srow + i * 8, bytes);
        }
        const __half* bsrc = WT + (size_t)c * 8192 + tid * 32;
        uint32_t bd = sb + 16384 + tid * 64;
#pragma unroll
        for (int i = 0; i < 4; ++i) cp_async16_ca(bd + i * 16, bsrc + i * 8);
        cp_commit();
    };

    // --- warp tiling + ldmatrix lane address components ---
    const int wm = wid & 3;          // m-warp (rows 32*wm)
    const int wn = wid >> 2;         // n-warp (cols 64*wn)

    uint32_t a_rowoff[2];
    int      a_ph[2];
#pragma unroll
    for (int mt = 0; mt < 2; ++mt) {
        int r = 32 * wm + 16 * mt + (lane & 15);
        a_rowoff[mt] = r * 128;
        a_ph[mt]     = r & 7;
    }
    const int a_kbh = lane >> 4;

    uint32_t b_rowoff[4];
    int      b_ph[4];
#pragma unroll
    for (int np = 0; np < 4; ++np) {
        int r = 64 * wn + 16 * np + (lane & 7) + ((lane >> 4) << 3);
        b_rowoff[np] = r * 128;
        b_ph[np]     = r & 7;
    }
    const int b_kbh = (lane >> 3) & 1;

    float d[2][8][4];
#pragma unroll
    for (int mt = 0; mt < 2; ++mt)
#pragma unroll
        for (int nt = 0; nt < 8; ++nt)
#pragma unroll
            for (int j = 0; j < 4; ++j) d[mt][nt][j] = 0.0f;

    // prologue
    load_chunk(0);
    load_chunk(1);

    for (int c = 0; c < NC; ++c) {
        if (c < NC - 1) cp_wait<1>(); else cp_wait<0>();
        __syncthreads();

        if (c + 2 < NC) load_chunk(c + 2);   // issue prefetch BEFORE compute

        uint32_t sb    = dsm_u32 + STAGES_OFF + (c % NSTAGE) * STAGE_BYTES;
        uint32_t bbase = sb + 16384;

#pragma unroll
        for (int ks = 0; ks < 4; ++ks) {              // 4 x k16 = K64
            uint32_t a0[4], a1[4];
            ldsm4(a0, sb + a_rowoff[0] + ((((ks << 1) | a_kbh) ^ a_ph[0]) << 4));
            ldsm4(a1, sb + a_rowoff[1] + ((((ks << 1) | a_kbh) ^ a_ph[1]) << 4));
#pragma unroll
            for (int np = 0; np < 4; ++np) {
                uint32_t b[4];
                ldsm4(b, bbase + b_rowoff[np] + ((((ks << 1) | b_kbh) ^ b_ph[np]) << 4));
                mma_f16(d[0][2 * np],     a0, b[0], b[1]);
                mma_f16(d[0][2 * np + 1], a0, b[2], b[3]);
                mma_f16(d[1][2 * np],     a1, b[0], b[1]);
                mma_f16(d[1][2 * np + 1], a1, b[2], b[3]);
            }
        }
        // no trailing barrier: next iteration's barrier provides the fence
    }

    const int qr = lane >> 2;            // 0..7
    const int qc = (lane & 3) * 2;       // 0,2,4,6

    // add bias into accumulators (needed before LN in fused path too)
#pragma unroll
    for (int mt = 0; mt < 2; ++mt)
#pragma unroll
        for (int nt = 0; nt < 8; ++nt) {
            float2 bb = *reinterpret_cast<const float2*>(bias + 64 * wn + 8 * nt + qc);
            d[mt][nt][0] += bb.x; d[mt][nt][1] += bb.y;
            d[mt][nt][2] += bb.x; d[mt][nt][3] += bb.y;
        }

    if (!FUSE_LN) {
        // --- epilogue: out = acc(+bias) + residual (fp32) ---
#pragma unroll
        for (int mt = 0; mt < 2; ++mt) {
#pragma unroll
            for (int nt = 0; nt < 8; ++nt) {
                int gc = 64 * wn + 8 * nt + qc;
                int gr0 = row0 + 32 * wm + 16 * mt + qr;
                int gr1 = gr0 + 8;
                if (gr0 < n) {
                    size_t off = (size_t)gr0 * C + gc;
                    float2 r = *reinterpret_cast<const float2*>(residual + off);
                    *reinterpret_cast<float2*>(out + off) =
                        make_float2(d[mt][nt][0] + r.x, d[mt][nt][1] + r.y);
                }
                if (gr1 < n) {
                    size_t off = (size_t)gr1 * C + gc;
                    float2 r = *reinterpret_cast<const float2*>(residual + off);
                    *reinterpret_cast<float2*>(out + off) =
                        make_float2(d[mt][nt][2] + r.x, d[mt][nt][3] + r.y);
                }
            }
        }
    } else {
        // --- fused epilogue: shuffle-based LN + FiLM + SiLU -> fp16 h3 ---
        // Row stats: each thread sums its 16 cols per row; reduce over the
        // lane-quad (xor 1,2) -> 64-col half sums; exchange across the two
        // n-warps via 2KB smem; combine; normalize in registers.
        float2* sbuf = reinterpret_cast<float2*>(dsm);   // [row][wn] = (s, ss)

        float s[2][2], ssq[2][2];   // [mt][rowhalf]
#pragma unroll
        for (int mt = 0; mt < 2; ++mt) {
            float s0 = 0.f, q0 = 0.f, s1 = 0.f, q1 = 0.f;
#pragma unroll
            for (int nt = 0; nt < 8; ++nt) {
                s0 += d[mt][nt][0] + d[mt][nt][1];
                q0 += d[mt][nt][0] * d[mt][nt][0] + d[mt][nt][1] * d[mt][nt][1];
                s1 += d[mt][nt][2] + d[mt][nt][3];
                q1 += d[mt][nt][2] * d[mt][nt][2] + d[mt][nt][3] * d[mt][nt][3];
            }
#pragma unroll
            for (int o = 1; o <= 2; o <<= 1) {
                s0 += __shfl_xor_sync(0xffffffffu, s0, o);
                q0 += __shfl_xor_sync(0xffffffffu, q0, o);
                s1 += __shfl_xor_sync(0xffffffffu, s1, o);
                q1 += __shfl_xor_sync(0xffffffffu, q1, o);
            }
            s[mt][0] = s0; ssq[mt][0] = q0;
            s[mt][1] = s1; ssq[mt][1] = q1;
        }
        if ((lane & 3) == 0) {
#pragma unroll
            for (int mt = 0; mt < 2; ++mt) {
                int r0 = 32 * wm + 16 * mt + qr;
                sbuf[r0 * 2 + wn]       = make_float2(s[mt][0], ssq[mt][0]);
                sbuf[(r0 + 8) * 2 + wn] = make_float2(s[mt][1], ssq[mt][1]);
            }
        }
        __syncthreads();

#pragma unroll
        for (int mt = 0; mt < 2; ++mt) {
#pragma unroll
            for (int rh = 0; rh < 2; ++rh) {
                int rl = 32 * wm + 16 * mt + qr + rh * 8;
                int gr = row0 + rl;
                if (gr < n) {
                    float2 p0 = sbuf[rl * 2 + 0];
                    float2 p1 = sbuf[rl * 2 + 1];
                    float mu  = (p0.x + p1.x) * (1.0f / 128.0f);
                    float var = (p0.y + p1.y) * (1.0f / 128.0f) - mu * mu;
                    float inv = rsqrtf(var + 1e-6f);
                    int b = batch_idx[gr];
                    const float* fs = g_film + b * 256;
#pragma unroll
                    for (int nt = 0; nt < 8; ++nt) {
                        int gc = 64 * wn + 8 * nt + qc;
                        float2 sc = *reinterpret_cast<const float2*>(fs + gc);
                        float2 sh = *reinterpret_cast<const float2*>(fs + 128 + gc);
                        float v0 = d[mt][nt][rh * 2 + 0];
                        float v1 = d[mt][nt][rh * 2 + 1];
                        float y0 = silu_f((v0 - mu) * inv * sc.x + sh.x);
                        float y1 = silu_f((v1 - mu) * inv * sc.y + sh.y);
                        *reinterpret_cast<__half2*>(h3_out + (size_t)gr * C + gc) =
                            __floats2half2_rn(y0, y1);
                    }
                }
            }
        }
    }
}

// ---------------------------------------------------------------------------
// Host launcher.
// ---------------------------------------------------------------------------
extern "C" void kernel_launch(void* const* d_in, const int* in_sizes, int n_in,
                              void* d_out, int out_size) {
    const float* feats = (const float*)d_in[0];
    const float* emb   = (const float*)d_in[1];
    const float* g1    = (const float*)d_in[2];
    const float* b1    = (const float*)d_in[3];
    const float* W1    = (const float*)d_in[4];
    const float* cb1   = (const float*)d_in[5];
    const float* W2    = (const float*)d_in[6];
    const float* cb2   = (const float*)d_in[7];
    const float* embW  = (const float*)d_in[8];
    const float* embb  = (const float*)d_in[9];
    const int*   nbr   = (const int*)d_in[10];
    const int*   bidx  = (const int*)d_in[11];
    float*       out   = (float*)d_out;
    (void)n_in; (void)out_size;

    const int n    = in_sizes[0] / C;                  // 200000
    const int nblk = (n + ROWS_CTA - 1) / ROWS_CTA;    // 1563

    cudaFuncSetAttribute(conv_mma_kernel<true>,
                         cudaFuncAttributeMaxDynamicSharedMemorySize, DYN_SMEM);
    cudaFuncSetAttribute(conv_mma_kernel<false>,
                         cudaFuncAttributeMaxDynamicSharedMemorySize, DYN_SMEM);

    __half *bufA, *bufH3, *wt1, *wt2;
    cudaGetSymbolAddress((void**)&bufA, g_bufA);
    cudaGetSymbolAddress((void**)&bufH3, g_bufH3);
    cudaGetSymbolAddress((void**)&wt1, g_WT1);
    cudaGetSymbolAddress((void**)&wt2, g_WT2);

    prep_kernel<<<2 * NC + 4, 256>>>(W1, W2, emb, embW, embb);             // 1
    ln_silu_kernel<<<n / 8, 256>>>(feats, g1, b1);                         // 2
    conv_mma_kernel<true><<<nblk, 256, DYN_SMEM>>>(bufA, nbr, wt1, cb1,    // 3
                                                   nullptr, nullptr, bufH3, bidx, n);
    conv_mma_kernel<false><<<nblk, 256, DYN_SMEM>>>(bufH3, nbr, wt2, cb2,  // 4 (profiled)
                                                    feats, out, nullptr, nullptr, n);
}